// round 14
// baseline (speedup 1.0000x reference)
#include <cuda_runtime.h>
#include <cuda_fp16.h>
#include <cstdint>

// ============================================================================
// LoRA layer as one fp16-input / fp32-accumulate GEMM on mma.sync (ptxas
// targets sm_103 plain — no tcgen05 available).
//   out[8192,2048] = x[8192,2048] @ (W + A@B)[2048,2048]
//   1) convert_x:   x fp32 -> fp16                         (g_x, [M,K])
//   2) build_weffT: (W + A@B)^T -> fp16                    (g_WT, [N,K])
//   3) gemm: 128x128 CTA tile, BK=64 (128B rows), 256 thr (8 warps,
//      64x32 warp tile), 3-stage cp.async (96 KB -> 2 CTAs/SM),
//      ldmatrix + mma.m16n8k16.f16
// Round-13 change vs R12 (235.6us): identical warp microkernel; CTA tile
// 128x256 -> 128x128 with 3 stages so 2 CTAs/SM and grid=1024 (6.92 waves,
// ~1% wave-quantization loss vs 13.5% at grid=512).
// ============================================================================

#define M_DIM 8192
#define N_DIM 2048
#define K_DIM 2048

#define BM 128
#define BN 128
#define BK 64                      // fp16 elems (128 bytes) per row per stage
#define STAGES 3
#define KITERS (K_DIM / BK)        // 32

#define A_STAGE_BYTES (BM * 128)   // 16 KB
#define B_STAGE_BYTES (BN * 128)   // 16 KB
#define STAGE_BYTES (A_STAGE_BYTES + B_STAGE_BYTES)   // 32 KB
#define SMEM_TOTAL (STAGES * STAGE_BYTES)             // 96 KB -> 2 CTAs/SM

__device__ __half g_x[(size_t)M_DIM * K_DIM];    // x as fp16, [M,K]
__device__ __half g_WT[(size_t)N_DIM * K_DIM];   // (W+AB)^T fp16, [N,K]

// ---------------------------------------------------------------------------
// helpers
// ---------------------------------------------------------------------------
__device__ __forceinline__ uint32_t smem_u32(const void* p) {
    uint32_t a;
    asm("{ .reg .u64 t; cvta.to.shared.u64 t, %1; cvt.u32.u64 %0, t; }"
        : "=r"(a) : "l"(p));
    return a;
}
__device__ __forceinline__ void cp_async16(uint32_t s, const void* g) {
    asm volatile("cp.async.cg.shared.global [%0], [%1], 16;"
                 :: "r"(s), "l"(g) : "memory");
}
__device__ __forceinline__ void cp_commit() {
    asm volatile("cp.async.commit_group;" ::: "memory");
}
template <int N> __device__ __forceinline__ void cp_wait() {
    asm volatile("cp.async.wait_group %0;" :: "n"(N) : "memory");
}
__device__ __forceinline__ void ldsm_x4(uint32_t* r, uint32_t addr) {
    asm volatile("ldmatrix.sync.aligned.m8n8.x4.shared.b16 {%0,%1,%2,%3}, [%4];"
                 : "=r"(r[0]), "=r"(r[1]), "=r"(r[2]), "=r"(r[3]) : "r"(addr));
}
__device__ __forceinline__ void ldsm_x2(uint32_t* r, uint32_t addr) {
    asm volatile("ldmatrix.sync.aligned.m8n8.x2.shared.b16 {%0,%1}, [%2];"
                 : "=r"(r[0]), "=r"(r[1]) : "r"(addr));
}
__device__ __forceinline__ void mma_f16(float* c, const uint32_t* a, const uint32_t* b) {
    asm volatile(
        "mma.sync.aligned.m16n8k16.row.col.f32.f16.f16.f32 "
        "{%0,%1,%2,%3}, {%4,%5,%6,%7}, {%8,%9}, {%0,%1,%2,%3};"
        : "+f"(c[0]), "+f"(c[1]), "+f"(c[2]), "+f"(c[3])
        : "r"(a[0]), "r"(a[1]), "r"(a[2]), "r"(a[3]), "r"(b[0]), "r"(b[1]));
}

// ---------------------------------------------------------------------------
// Kernel 1: x fp32 -> fp16
// ---------------------------------------------------------------------------
__global__ void convert_x_kernel(const float4* __restrict__ x, __half2* __restrict__ gx) {
    int idx = blockIdx.x * blockDim.x + threadIdx.x;   // float4 index
    float4 v = x[idx];
    gx[idx * 2 + 0] = __floats2half2_rn(v.x, v.y);
    gx[idx * 2 + 1] = __floats2half2_rn(v.z, v.w);
}

// ---------------------------------------------------------------------------
// Kernel 2: W_eff^T: out[n*K + c] = fp16( W[c*N + n] + sum_r A[c,r]*B[r,n] )
// ---------------------------------------------------------------------------
__global__ void build_weffT_kernel(const float* __restrict__ W,
                                   const float* __restrict__ A,
                                   const float* __restrict__ Bk,
                                   __half* __restrict__ out) {
    __shared__ float t[32][33];
    int ci = blockIdx.y * 32;
    int ni = blockIdx.x * 32;
    #pragma unroll
    for (int i = 0; i < 4; i++) {
        int c = ci + threadIdx.y + i * 8;
        int n = ni + threadIdx.x;
        float w = W[(size_t)c * N_DIM + n];
        float a0 = A[c * 4 + 0], a1 = A[c * 4 + 1], a2 = A[c * 4 + 2], a3 = A[c * 4 + 3];
        w += a0 * Bk[n] + a1 * Bk[N_DIM + n] + a2 * Bk[2 * N_DIM + n] + a3 * Bk[3 * N_DIM + n];
        t[threadIdx.y + i * 8][threadIdx.x] = w;
    }
    __syncthreads();
    #pragma unroll
    for (int i = 0; i < 4; i++) {
        int n = ni + threadIdx.y + i * 8;
        int c = ci + threadIdx.x;
        out[(size_t)n * K_DIM + c] = __float2half_rn(t[threadIdx.x][threadIdx.y + i * 8]);
    }
}

// ---------------------------------------------------------------------------
// Kernel 3: fp16 mma.sync GEMM, 128x128 per CTA, 256 threads
//   warp grid 2(M) x 4(N); warp tile 64x32: 4 m-tiles(16) x 4 n-tiles(8)
// smem row = 64 fp16 = 128B = 8 chunks of 16B, chunk swizzle c ^= (row & 7)
// Each k-iter (BK=64) = 4 k16 MMA steps. Microkernel identical to R12.
// ---------------------------------------------------------------------------
__global__ __launch_bounds__(256, 2)
void gemm_f16_mma(const __half* __restrict__ gA,   // [M,K]
                  const __half* __restrict__ gB,   // [N,K]
                  float* __restrict__ C) {
    extern __shared__ char smem[];
    const uint32_t sbase = smem_u32(smem);

    const int tid  = threadIdx.x;
    const int wid  = tid >> 5;
    const int lane = tid & 31;
    const int wm = wid & 1;        // 0..1  (M)
    const int wn = wid >> 1;       // 0..3  (N)

    const int bm = blockIdx.y;     // 0..63
    const int bn = blockIdx.x;     // 0..15

    // ---- cp.async mappings --------------------------------------------------
    // A: 128 rows x 8 chunks = 1024 chunks -> 4 per thread (2 threads/row)
    const int arow = tid >> 1;                 // 0..127
    const int ac0  = (tid & 1) * 4;            // chunks ac0..ac0+3
    // B: identical shape
    const int brow = arow;
    const int bc0  = ac0;

    const char* gAp = (const char*)(gA + (size_t)(bm * BM + arow) * K_DIM);
    const char* gBp = (const char*)(gB + (size_t)(bn * BN + brow) * K_DIM);

    auto load_stage = [&](int s) {
        uint32_t st = sbase + (s % STAGES) * STAGE_BYTES;
        uint32_t sa = st + arow * 128;
        uint32_t sb = st + A_STAGE_BYTES + brow * 128;
        const char* ga = gAp + (size_t)s * 128;   // BK=64 fp16 = 128B along K
        const char* gb = gBp + (size_t)s * 128;
        #pragma unroll
        for (int j = 0; j < 4; j++) {
            int c = ac0 + j;
            cp_async16(sa + ((c ^ (arow & 7)) << 4), ga + c * 16);
        }
        #pragma unroll
        for (int j = 0; j < 4; j++) {
            int c = bc0 + j;
            cp_async16(sb + ((c ^ (brow & 7)) << 4), gb + c * 16);
        }
    };

    // ---- ldmatrix address bases --------------------------------------------
    const int a_r = wm * 64 + (lane & 15);
    const int a_h = lane >> 4;            // 0/1
    const int r7  = lane & 7;
    const int b_r = wn * 32 + (lane & 7);
    const int b_h = (lane >> 3) & 1;

    float acc[4][4][4];
    #pragma unroll
    for (int i = 0; i < 4; i++)
        #pragma unroll
        for (int j = 0; j < 4; j++)
            #pragma unroll
            for (int q = 0; q < 4; q++)
                acc[i][j][q] = 0.0f;

    // ---- prologue ----------------------------------------------------------
    #pragma unroll
    for (int s = 0; s < STAGES - 1; s++) { load_stage(s); cp_commit(); }

    // ---- main loop ---------------------------------------------------------
    for (int k = 0; k < KITERS; k++) {
        cp_wait<STAGES - 2>();
        __syncthreads();

        uint32_t st = sbase + (k % STAGES) * STAGE_BYTES;
        uint32_t sa = st + a_r * 128;
        uint32_t sb = st + A_STAGE_BYTES + b_r * 128;

        #pragma unroll
        for (int ks = 0; ks < 4; ks++) {
            uint32_t afr[4][4];
            uint32_t bfr[4][2];
            const int ca = ((2 * ks + a_h) ^ r7) << 4;
            const int cb = ((2 * ks + b_h) ^ r7) << 4;
            #pragma unroll
            for (int mt = 0; mt < 4; mt++)
                ldsm_x4(afr[mt], sa + mt * (16 * 128) + ca);
            #pragma unroll
            for (int nt = 0; nt < 4; nt++)
                ldsm_x2(bfr[nt], sb + nt * (8 * 128) + cb);
            #pragma unroll
            for (int mt = 0; mt < 4; mt++)
                #pragma unroll
                for (int nt = 0; nt < 4; nt++)
                    mma_f16(acc[mt][nt], afr[mt], bfr[nt]);
        }

        if (k + STAGES - 1 < KITERS) load_stage(k + STAGES - 1);
        cp_commit();
    }

    // ---- epilogue ----------------------------------------------------------
    const int er = lane >> 2;
    const int ec = (lane & 3) * 2;
    #pragma unroll
    for (int mt = 0; mt < 4; mt++) {
        int m0 = bm * BM + wm * 64 + mt * 16 + er;
        #pragma unroll
        for (int nt = 0; nt < 4; nt++) {
            int n0 = bn * BN + wn * 32 + nt * 8 + ec;
            *(float2*)(C + (size_t)m0 * N_DIM + n0) =
                make_float2(acc[mt][nt][0], acc[mt][nt][1]);
            *(float2*)(C + (size_t)(m0 + 8) * N_DIM + n0) =
                make_float2(acc[mt][nt][2], acc[mt][nt][3]);
        }
    }
}

// ---------------------------------------------------------------------------
// Launch
// ---------------------------------------------------------------------------
extern "C" void kernel_launch(void* const* d_in, const int* in_sizes, int n_in,
                              void* d_out, int out_size) {
    const float* x  = (const float*)d_in[0];   // [8192, 2048]
    const float* W  = (const float*)d_in[1];   // [2048, 2048]
    const float* A  = (const float*)d_in[2];   // [2048, 4]
    const float* Bk = (const float*)d_in[3];   // [4, 2048]
    float* out = (float*)d_out;

    __half *gx, *gwt;
    cudaGetSymbolAddress((void**)&gx, g_x);
    cudaGetSymbolAddress((void**)&gwt, g_WT);

    // 1) x -> fp16
    {
        int total4 = (M_DIM * K_DIM) / 4;
        convert_x_kernel<<<total4 / 256, 256>>>((const float4*)x, (__half2*)gx);
    }
    // 2) W_eff^T -> fp16
    {
        dim3 grid(N_DIM / 32, K_DIM / 32);
        dim3 block(32, 8);
        build_weffT_kernel<<<grid, block>>>(W, A, Bk, gwt);
    }
    // 3) GEMM
    {
        static bool attr_set = false;
        if (!attr_set) {
            cudaFuncSetAttribute(gemm_f16_mma,
                                 cudaFuncAttributeMaxDynamicSharedMemorySize, SMEM_TOTAL);
            attr_set = true;
        }
        dim3 grid(N_DIM / BN, M_DIM / BM);   // (16, 64)
        gemm_f16_mma<<<grid, 256, SMEM_TOTAL>>>(gx, gwt, out);
    }
}